// round 14
// baseline (speedup 1.0000x reference)
#include <cuda_runtime.h>

#define EPS 1e-8f
#define STRIPH 64
#define NTHREADS 256
#define FULLMASK 0xffffffffu

// green-interp diff at a non-green site: returns m - g_interp
__device__ __forceinline__ float gdiff(float c, float xl, float xr, float yu, float yd,
                                       float gf0, float gf1, float gf2,
                                       float r0, float r1, float r2)
{
    float gh = gf0*xl + gf1*c + gf2*xr;
    float gv = gf0*yu + gf1*c + gf2*yd;
    float dx = r0*xl + r1*c + r2*xr;
    float dy = r0*yu + r1*c + r2*yd;
    float adx = fabsf(dx), ady = fabsf(dy);
    float w = __fdividef(ady, adx + ady + EPS);
    return c - (w*gh + (1.0f - w)*gv);
}

// Warp-register streaming demosaick. Each warp: 64-px-wide x 64-row strip.
// Lane l owns pixels (x0+2l, x0+2l+1). Even rows are G R, odd rows B G.
// Halo loads (q) predicated to lanes 0 / 31 only.
__global__ __launch_bounds__(NTHREADS, 4) void demosaick_kernel(
    const float* __restrict__ m,
    const float* __restrict__ gfilt,
    const float* __restrict__ grad_filt,
    float* __restrict__ out,
    int H, int W)
{
    const int lane = threadIdx.x & 31;
    const int wrp  = threadIdx.x >> 5;

    const int xblocks = W / 512;            // x-blocks of 8 warps * 64 px
    const int nys     = H / STRIPH;
    const int xb = blockIdx.x % xblocks;
    const int ys = (blockIdx.x / xblocks) % nys;
    const int b  = blockIdx.x / (xblocks * nys);

    const int x0 = (xb * 8 + wrp) * 64;
    const int y0 = ys * STRIPH;

    const float* __restrict__ mb = m + (size_t)b * H * W;
    const size_t img = (size_t)H * W;
    float* __restrict__ outr = out + (size_t)(b*3+0)*img;
    float* __restrict__ outg = out + (size_t)(b*3+1)*img;
    float* __restrict__ outb = out + (size_t)(b*3+2)*img;

    const float gf0 = gfilt[0], gf1 = gfilt[1], gf2 = gfilt[2];
    const float r0 = grad_filt[0], r1 = grad_filt[1], r2 = grad_filt[2];

    const bool xl0 = (x0 == 0);
    const bool xr0 = (x0 + 64 == W);
    const int offm = x0 + 2*lane;
    const bool rsel  = (lane == 31);
    const bool haloL = (lane == 0);
    const bool qact  = haloL | rsel;
    int offq = offm;
    if (haloL) offq = max(x0 - 2, 0);
    if (rsel)  offq = min(x0 + 64, W - 2);

    auto ld = [&](int y, int off) -> float2 {
        y = min(max(y, 0), H - 1);
        return *reinterpret_cast<const float2*>(mb + (size_t)y * W + off);
    };
    auto ldq = [&](int y) -> float2 {
        if (qact) return ld(y, offq);
        return make_float2(0.f, 0.f);
    };

    // ---------------- prologue: d[y0-1], d[y0], halo diffs ----------------
    float2 t0 = ld(y0-2, offm), t1 = ld(y0-1, offm), t2 = ld(y0, offm), t3 = ld(y0+1, offm);
    float2 q0 = ldq(y0-2), q1 = ldq(y0-1), q2 = ldq(y0), q3 = ldq(y0+1);

    float xlv = __shfl_up_sync(FULLMASK, t1.y, 1);
    if (haloL) xlv = xl0 ? t1.x : q1.y;
    float dOdd_prev = gdiff(t1.x, xlv, t1.y, t0.x, t2.x, gf0,gf1,gf2,r0,r1,r2);  // d[y0-1]

    float xrv = __shfl_down_sync(FULLMASK, t2.x, 1);
    if (rsel) xrv = xr0 ? t2.y : q2.x;
    float dEv_cur = gdiff(t2.y, t2.x, xrv, t1.y, t3.y, gf0,gf1,gf2,r0,r1,r2);    // d[y0]

    float hL_cur, hR_prev;
    {
        // lane31: right halo diff @ row y0-1 (odd); lane0: left halo diff @ row y0 (even)
        float hc  = rsel ? q1.x : q2.y;
        float hxl = rsel ? t1.y : q2.x;
        float hxr = rsel ? q1.y : t2.x;
        float hyu = rsel ? q0.x : q1.y;
        float hyd = rsel ? q2.x : q3.y;
        float h = gdiff(hc,hxl,hxr,hyu,hyd, gf0,gf1,gf2,r0,r1,r2);
        hL_cur = h; hR_prev = h;
    }

    float2 mA = t2, mB = t3;
    float2 mC = ld(y0+2, offm), mD = ld(y0+3, offm);
    float2 qA = q2, qB = q3;
    float2 qC = ldq(y0+2), qD = ldq(y0+3);

    // ---------------- main march: 2 rows per iteration ----------------
    #pragma unroll 4
    for (int y = y0; y < y0 + STRIPH; y += 2) {
        // d[y+1] (odd row): site .x
        float a = __shfl_up_sync(FULLMASK, mB.y, 1);
        if (haloL) a = xl0 ? mB.x : qB.y;
        float dOdd_cur = gdiff(mB.x, a, mB.y, mA.x, mC.x, gf0,gf1,gf2,r0,r1,r2);

        // d[y+2] (even row): site .y
        float bb = __shfl_down_sync(FULLMASK, mC.x, 1);
        if (rsel) bb = xr0 ? mC.y : qC.x;
        float dEv_next = gdiff(mC.y, mC.x, bb, mB.y, mD.y, gf0,gf1,gf2,r0,r1,r2);

        // combined halo diff: lane31 -> right @ y+1 (odd), lane0 -> left @ y+2 (even)
        float hc  = rsel ? qB.x : qC.y;
        float hxl = rsel ? mB.y : qC.x;
        float hxr = rsel ? qB.y : mC.x;
        float hyu = rsel ? qA.x : qB.y;
        float hyd = rsel ? qC.x : qD.y;
        float h = gdiff(hc,hxl,hxr,hyu,hyd, gf0,gf1,gf2,r0,r1,r2);
        float hL_next = h;     // valid on lane 0
        float hR_cur  = h;     // valid on lane 31

        // prefetch next window rows while chroma computes
        float2 nmC = ld(y+4, offm), nmD = ld(y+5, offm);
        float2 nqC = ldq(y+4),      nqD = ldq(y+5);

        const size_t o = (size_t)y * W + offm;

        // ---- chroma even row y (G R) ----
        {
            float dCo = dEv_cur;
            float dLo = __shfl_up_sync(FULLMASK, dEv_cur, 1);
            if (haloL) dLo = xl0 ? dCo : hL_cur;
            float du0 = dOdd_prev, dd0 = dOdd_cur;
            float du2 = __shfl_down_sync(FULLMASK, dOdd_prev, 1);
            float dd2 = __shfl_down_sync(FULLMASK, dOdd_cur, 1);
            if (rsel) { du2 = xr0 ? du0 : hR_prev; dd2 = xr0 ? dd0 : hR_cur; }
            if (y == 0) { du0 = dd0; du2 = dd2; }      // zero-pad mirror at top

            float2 G, R, Bv;
            G.x = mA.x;               G.y = mA.y - dCo;
            R.x = G.x + 0.5f*(dLo + dCo);   R.y = mA.y;
            Bv.x = G.x + 0.5f*(du0 + dd0);
            Bv.y = G.y + 0.25f*(du0 + du2 + dd0 + dd2);

            __stcs(reinterpret_cast<float2*>(outr + o), R);
            __stcs(reinterpret_cast<float2*>(outg + o), G);
            __stcs(reinterpret_cast<float2*>(outb + o), Bv);
        }

        // ---- chroma odd row y+1 (B G) ----
        {
            float d0 = dOdd_cur;
            float d2 = __shfl_down_sync(FULLMASK, dOdd_cur, 1);
            if (rsel) d2 = xr0 ? d0 : hR_cur;
            float dub = dEv_cur, ddb = dEv_next;
            float dua = __shfl_up_sync(FULLMASK, dEv_cur, 1);
            float dda = __shfl_up_sync(FULLMASK, dEv_next, 1);
            if (haloL) { dua = xl0 ? dub : hL_cur; dda = xl0 ? ddb : hL_next; }
            if (y + 1 == H - 1) { dda = dua; ddb = dub; }   // zero-pad mirror at bottom

            float2 G, R, Bv;
            G.x = mB.x - d0;          G.y = mB.y;
            Bv.x = mB.x;              Bv.y = G.y + 0.5f*(d0 + d2);
            R.x = G.x + 0.25f*(dua + dub + dda + ddb);
            R.y = G.y + 0.5f*(dub + ddb);

            __stcs(reinterpret_cast<float2*>(outr + o + W), R);
            __stcs(reinterpret_cast<float2*>(outg + o + W), G);
            __stcs(reinterpret_cast<float2*>(outb + o + W), Bv);
        }

        // ---- shift pipeline ----
        mA = mC; mB = mD; mC = nmC; mD = nmD;
        qA = qC; qB = qD; qC = nqC; qD = nqD;
        dOdd_prev = dOdd_cur; dEv_cur = dEv_next;
        hL_cur = hL_next; hR_prev = hR_cur;
    }
}

extern "C" void kernel_launch(void* const* d_in, const int* in_sizes, int n_in,
                              void* d_out, int out_size)
{
    const float* m         = (const float*)d_in[0];
    const float* gfilt     = (const float*)d_in[1];
    const float* grad_filt = (const float*)d_in[2];
    float* out             = (float*)d_out;

    const int H = 1024, W = 1024;
    const int B = in_sizes[0] / (H * W);

    const int xblocks = W / 512;             // 8 warps * 64 px
    const int nys     = H / STRIPH;
    dim3 grid(xblocks * nys * B);
    demosaick_kernel<<<grid, NTHREADS>>>(m, gfilt, grad_filt, out, H, W);
}

// round 15
// speedup vs baseline: 1.0078x; 1.0078x over previous
#include <cuda_runtime.h>

#define EPS 1e-8f
#define STRIPH 32
#define NTHREADS 256
#define FULLMASK 0xffffffffu

// green-interp diff at a non-green site: returns m - g_interp
__device__ __forceinline__ float gdiff(float c, float xl, float xr, float yu, float yd,
                                       float gf0, float gf1, float gf2,
                                       float r0, float r1, float r2)
{
    float gh = gf0*xl + gf1*c + gf2*xr;
    float gv = gf0*yu + gf1*c + gf2*yd;
    float dx = r0*xl + r1*c + r2*xr;
    float dy = r0*yu + r1*c + r2*yd;
    float adx = fabsf(dx), ady = fabsf(dy);
    float w = __fdividef(ady, adx + ady + EPS);
    return c - (w*gh + (1.0f - w)*gv);
}

// Warp-register streaming demosaick. Each warp: 64-px-wide x 32-row strip.
// Lane l owns pixels (x0+2l, x0+2l+1). Even rows are G R, odd rows B G.
// Halo loads (q) predicated to lanes 0 / 31 only.
__global__ __launch_bounds__(NTHREADS, 4) void demosaick_kernel(
    const float* __restrict__ m,
    const float* __restrict__ gfilt,
    const float* __restrict__ grad_filt,
    float* __restrict__ out,
    int H, int W)
{
    const int lane = threadIdx.x & 31;
    const int wrp  = threadIdx.x >> 5;

    const int xblocks = W / 512;            // x-blocks of 8 warps * 64 px
    const int nys     = H / STRIPH;
    const int xb = blockIdx.x % xblocks;
    const int ys = (blockIdx.x / xblocks) % nys;
    const int b  = blockIdx.x / (xblocks * nys);

    const int x0 = (xb * 8 + wrp) * 64;
    const int y0 = ys * STRIPH;

    const float* __restrict__ mb = m + (size_t)b * H * W;
    const size_t img = (size_t)H * W;
    float* __restrict__ outr = out + (size_t)(b*3+0)*img;
    float* __restrict__ outg = out + (size_t)(b*3+1)*img;
    float* __restrict__ outb = out + (size_t)(b*3+2)*img;

    const float gf0 = gfilt[0], gf1 = gfilt[1], gf2 = gfilt[2];
    const float r0 = grad_filt[0], r1 = grad_filt[1], r2 = grad_filt[2];

    const bool xl0 = (x0 == 0);
    const bool xr0 = (x0 + 64 == W);
    const int offm = x0 + 2*lane;
    const bool rsel  = (lane == 31);
    const bool haloL = (lane == 0);
    const bool qact  = haloL | rsel;
    int offq = offm;
    if (haloL) offq = max(x0 - 2, 0);
    if (rsel)  offq = min(x0 + 64, W - 2);

    auto ld = [&](int y, int off) -> float2 {
        y = min(max(y, 0), H - 1);
        return *reinterpret_cast<const float2*>(mb + (unsigned)(y * W) + off);
    };
    auto ldq = [&](int y) -> float2 {
        if (qact) return ld(y, offq);
        return make_float2(0.f, 0.f);
    };

    // ---------------- prologue: d[y0-1], d[y0], halo diffs ----------------
    float2 t0 = ld(y0-2, offm), t1 = ld(y0-1, offm), t2 = ld(y0, offm), t3 = ld(y0+1, offm);
    float2 q0 = ldq(y0-2), q1 = ldq(y0-1), q2 = ldq(y0), q3 = ldq(y0+1);

    float xlv = __shfl_up_sync(FULLMASK, t1.y, 1);
    if (haloL) xlv = xl0 ? t1.x : q1.y;
    float dOdd_prev = gdiff(t1.x, xlv, t1.y, t0.x, t2.x, gf0,gf1,gf2,r0,r1,r2);  // d[y0-1]

    float xrv = __shfl_down_sync(FULLMASK, t2.x, 1);
    if (rsel) xrv = xr0 ? t2.y : q2.x;
    float dEv_cur = gdiff(t2.y, t2.x, xrv, t1.y, t3.y, gf0,gf1,gf2,r0,r1,r2);    // d[y0]

    float hL_cur, hR_prev;
    {
        // lane31: right halo diff @ row y0-1 (odd); lane0: left halo diff @ row y0 (even)
        float hc  = rsel ? q1.x : q2.y;
        float hxl = rsel ? t1.y : q2.x;
        float hxr = rsel ? q1.y : t2.x;
        float hyu = rsel ? q0.x : q1.y;
        float hyd = rsel ? q2.x : q3.y;
        float h = gdiff(hc,hxl,hxr,hyu,hyd, gf0,gf1,gf2,r0,r1,r2);
        hL_cur = h; hR_prev = h;
    }

    float2 mA = t2, mB = t3;
    float2 mC = ld(y0+2, offm), mD = ld(y0+3, offm);
    float2 qA = q2, qB = q3;
    float2 qC = ldq(y0+2), qD = ldq(y0+3);

    // ---------------- main march: 2 rows per iteration ----------------
    #pragma unroll 4
    for (int r = 0; r < STRIPH; r += 2) {
        const int y = y0 + r;

        // d[y+1] (odd row): site .x
        float a = __shfl_up_sync(FULLMASK, mB.y, 1);
        if (haloL) a = xl0 ? mB.x : qB.y;
        float dOdd_cur = gdiff(mB.x, a, mB.y, mA.x, mC.x, gf0,gf1,gf2,r0,r1,r2);

        // d[y+2] (even row): site .y
        float bb = __shfl_down_sync(FULLMASK, mC.x, 1);
        if (rsel) bb = xr0 ? mC.y : qC.x;
        float dEv_next = gdiff(mC.y, mC.x, bb, mB.y, mD.y, gf0,gf1,gf2,r0,r1,r2);

        // combined halo diff: lane31 -> right @ y+1 (odd), lane0 -> left @ y+2 (even)
        float hc  = rsel ? qB.x : qC.y;
        float hxl = rsel ? mB.y : qC.x;
        float hxr = rsel ? qB.y : mC.x;
        float hyu = rsel ? qA.x : qB.y;
        float hyd = rsel ? qC.x : qD.y;
        float h = gdiff(hc,hxl,hxr,hyu,hyd, gf0,gf1,gf2,r0,r1,r2);
        float hL_next = h;     // valid on lane 0
        float hR_cur  = h;     // valid on lane 31

        // prefetch next window rows while chroma computes (skip dead last prefetch)
        float2 nmC = mC, nmD = mD, nqC = qC, nqD = qD;
        if (r + 2 < STRIPH) {
            nmC = ld(y+4, offm); nmD = ld(y+5, offm);
            nqC = ldq(y+4);      nqD = ldq(y+5);
        }

        const unsigned o = (unsigned)(y * W) + offm;

        // ---- chroma even row y (G R) ----
        {
            float dCo = dEv_cur;
            float dLo = __shfl_up_sync(FULLMASK, dEv_cur, 1);
            if (haloL) dLo = xl0 ? dCo : hL_cur;
            float du0 = dOdd_prev, dd0 = dOdd_cur;
            float du2 = __shfl_down_sync(FULLMASK, dOdd_prev, 1);
            float dd2 = __shfl_down_sync(FULLMASK, dOdd_cur, 1);
            if (rsel) { du2 = xr0 ? du0 : hR_prev; dd2 = xr0 ? dd0 : hR_cur; }
            if (y == 0) { du0 = dd0; du2 = dd2; }      // zero-pad mirror at top

            float2 G, R, Bv;
            G.x = mA.x;               G.y = mA.y - dCo;
            R.x = G.x + 0.5f*(dLo + dCo);   R.y = mA.y;
            Bv.x = G.x + 0.5f*(du0 + dd0);
            Bv.y = G.y + 0.25f*(du0 + du2 + dd0 + dd2);

            __stcs(reinterpret_cast<float2*>(outr + o), R);
            __stcs(reinterpret_cast<float2*>(outg + o), G);
            __stcs(reinterpret_cast<float2*>(outb + o), Bv);
        }

        // ---- chroma odd row y+1 (B G) ----
        {
            float d0 = dOdd_cur;
            float d2 = __shfl_down_sync(FULLMASK, dOdd_cur, 1);
            if (rsel) d2 = xr0 ? d0 : hR_cur;
            float dub = dEv_cur, ddb = dEv_next;
            float dua = __shfl_up_sync(FULLMASK, dEv_cur, 1);
            float dda = __shfl_up_sync(FULLMASK, dEv_next, 1);
            if (haloL) { dua = xl0 ? dub : hL_cur; dda = xl0 ? ddb : hL_next; }
            if (y + 1 == H - 1) { dda = dua; ddb = dub; }   // zero-pad mirror at bottom

            float2 G, R, Bv;
            G.x = mB.x - d0;          G.y = mB.y;
            Bv.x = mB.x;              Bv.y = G.y + 0.5f*(d0 + d2);
            R.x = G.x + 0.25f*(dua + dub + dda + ddb);
            R.y = G.y + 0.5f*(dub + ddb);

            __stcs(reinterpret_cast<float2*>(outr + o + W), R);
            __stcs(reinterpret_cast<float2*>(outg + o + W), G);
            __stcs(reinterpret_cast<float2*>(outb + o + W), Bv);
        }

        // ---- shift pipeline ----
        mA = mC; mB = mD; mC = nmC; mD = nmD;
        qA = qC; qB = qD; qC = nqC; qD = nqD;
        dOdd_prev = dOdd_cur; dEv_cur = dEv_next;
        hL_cur = hL_next; hR_prev = hR_cur;
    }
}

extern "C" void kernel_launch(void* const* d_in, const int* in_sizes, int n_in,
                              void* d_out, int out_size)
{
    const float* m         = (const float*)d_in[0];
    const float* gfilt     = (const float*)d_in[1];
    const float* grad_filt = (const float*)d_in[2];
    float* out             = (float*)d_out;

    const int H = 1024, W = 1024;
    const int B = in_sizes[0] / (H * W);

    const int xblocks = W / 512;             // 8 warps * 64 px
    const int nys     = H / STRIPH;
    dim3 grid(xblocks * nys * B);
    demosaick_kernel<<<grid, NTHREADS>>>(m, gfilt, grad_filt, out, H, W);
}

// round 16
// speedup vs baseline: 1.0602x; 1.0521x over previous
#include <cuda_runtime.h>

#define EPS 1e-8f
#define STRIPH 32
#define NTHREADS 256
#define FULLMASK 0xffffffffu

// green-interp diff at a non-green site: returns m - g_interp
__device__ __forceinline__ float gdiff(float c, float xl, float xr, float yu, float yd,
                                       float gf0, float gf1, float gf2,
                                       float r0, float r1, float r2)
{
    float gh = gf0*xl + gf1*c + gf2*xr;
    float gv = gf0*yu + gf1*c + gf2*yd;
    float dx = r0*xl + r1*c + r2*xr;
    float dy = r0*yu + r1*c + r2*yd;
    float adx = fabsf(dx), ady = fabsf(dy);
    float w = __fdividef(ady, adx + ady + EPS);
    return c - (w*gh + (1.0f - w)*gv);
}

// Warp-register streaming demosaick. Each warp: 64-px-wide x 32-row strip.
// Lane l owns pixels (x0+2l, x0+2l+1). Even rows are G R, odd rows B G.
// Halo loads (q) predicated to lanes 0 / 31 only.
__global__ __launch_bounds__(NTHREADS) void demosaick_kernel(
    const float* __restrict__ m,
    const float* __restrict__ gfilt,
    const float* __restrict__ grad_filt,
    float* __restrict__ out,
    int H, int W)
{
    const int lane = threadIdx.x & 31;
    const int wrp  = threadIdx.x >> 5;

    const int xblocks = W / 512;            // x-blocks of 8 warps * 64 px
    const int nys     = H / STRIPH;
    const int xb = blockIdx.x % xblocks;
    const int ys = (blockIdx.x / xblocks) % nys;
    const int b  = blockIdx.x / (xblocks * nys);

    const int x0 = (xb * 8 + wrp) * 64;
    const int y0 = ys * STRIPH;

    const float* __restrict__ mb = m + (size_t)b * H * W;
    const size_t img = (size_t)H * W;
    float* __restrict__ outr = out + (size_t)(b*3+0)*img;
    float* __restrict__ outg = out + (size_t)(b*3+1)*img;
    float* __restrict__ outb = out + (size_t)(b*3+2)*img;

    const float gf0 = gfilt[0], gf1 = gfilt[1], gf2 = gfilt[2];
    const float r0 = grad_filt[0], r1 = grad_filt[1], r2 = grad_filt[2];

    const bool xl0 = (x0 == 0);
    const bool xr0 = (x0 + 64 == W);
    const int offm = x0 + 2*lane;
    const bool rsel  = (lane == 31);
    const bool haloL = (lane == 0);
    const bool qact  = haloL | rsel;
    int offq = offm;
    if (haloL) offq = max(x0 - 2, 0);
    if (rsel)  offq = min(x0 + 64, W - 2);

    auto ld = [&](int y, int off) -> float2 {
        y = min(max(y, 0), H - 1);
        return *reinterpret_cast<const float2*>(mb + (size_t)y * W + off);
    };
    auto ldq = [&](int y) -> float2 {
        if (qact) return ld(y, offq);
        return make_float2(0.f, 0.f);
    };

    // ---------------- prologue: d[y0-1], d[y0], halo diffs ----------------
    float2 t0 = ld(y0-2, offm), t1 = ld(y0-1, offm), t2 = ld(y0, offm), t3 = ld(y0+1, offm);
    float2 q0 = ldq(y0-2), q1 = ldq(y0-1), q2 = ldq(y0), q3 = ldq(y0+1);

    float xlv = __shfl_up_sync(FULLMASK, t1.y, 1);
    if (haloL) xlv = xl0 ? t1.x : q1.y;
    float dOdd_prev = gdiff(t1.x, xlv, t1.y, t0.x, t2.x, gf0,gf1,gf2,r0,r1,r2);  // d[y0-1]

    float xrv = __shfl_down_sync(FULLMASK, t2.x, 1);
    if (rsel) xrv = xr0 ? t2.y : q2.x;
    float dEv_cur = gdiff(t2.y, t2.x, xrv, t1.y, t3.y, gf0,gf1,gf2,r0,r1,r2);    // d[y0]

    float hL_cur, hR_prev;
    {
        // lane31: right halo diff @ row y0-1 (odd); lane0: left halo diff @ row y0 (even)
        float hc  = rsel ? q1.x : q2.y;
        float hxl = rsel ? t1.y : q2.x;
        float hxr = rsel ? q1.y : t2.x;
        float hyu = rsel ? q0.x : q1.y;
        float hyd = rsel ? q2.x : q3.y;
        float h = gdiff(hc,hxl,hxr,hyu,hyd, gf0,gf1,gf2,r0,r1,r2);
        hL_cur = h; hR_prev = h;
    }

    float2 mA = t2, mB = t3;
    float2 mC = ld(y0+2, offm), mD = ld(y0+3, offm);
    float2 qA = q2, qB = q3;
    float2 qC = ldq(y0+2), qD = ldq(y0+3);

    // ---------------- main march: 2 rows per iteration ----------------
    #pragma unroll 4
    for (int y = y0; y < y0 + STRIPH; y += 2) {
        // prefetch next window rows FIRST — maximizes load->consume distance
        float2 nmC = ld(y+4, offm), nmD = ld(y+5, offm);
        float2 nqC = ldq(y+4),      nqD = ldq(y+5);

        // d[y+1] (odd row): site .x
        float a = __shfl_up_sync(FULLMASK, mB.y, 1);
        if (haloL) a = xl0 ? mB.x : qB.y;
        float dOdd_cur = gdiff(mB.x, a, mB.y, mA.x, mC.x, gf0,gf1,gf2,r0,r1,r2);

        // d[y+2] (even row): site .y
        float bb = __shfl_down_sync(FULLMASK, mC.x, 1);
        if (rsel) bb = xr0 ? mC.y : qC.x;
        float dEv_next = gdiff(mC.y, mC.x, bb, mB.y, mD.y, gf0,gf1,gf2,r0,r1,r2);

        // combined halo diff: lane31 -> right @ y+1 (odd), lane0 -> left @ y+2 (even)
        float hc  = rsel ? qB.x : qC.y;
        float hxl = rsel ? mB.y : qC.x;
        float hxr = rsel ? qB.y : mC.x;
        float hyu = rsel ? qA.x : qB.y;
        float hyd = rsel ? qC.x : qD.y;
        float h = gdiff(hc,hxl,hxr,hyu,hyd, gf0,gf1,gf2,r0,r1,r2);
        float hL_next = h;     // valid on lane 0
        float hR_cur  = h;     // valid on lane 31

        const size_t o = (size_t)y * W + offm;

        // ---- chroma even row y (G R) ----
        {
            float dCo = dEv_cur;
            float dLo = __shfl_up_sync(FULLMASK, dEv_cur, 1);
            if (haloL) dLo = xl0 ? dCo : hL_cur;
            float du0 = dOdd_prev, dd0 = dOdd_cur;
            float du2 = __shfl_down_sync(FULLMASK, dOdd_prev, 1);
            float dd2 = __shfl_down_sync(FULLMASK, dOdd_cur, 1);
            if (rsel) { du2 = xr0 ? du0 : hR_prev; dd2 = xr0 ? dd0 : hR_cur; }
            if (y == 0) { du0 = dd0; du2 = dd2; }      // zero-pad mirror at top

            float2 G, R, Bv;
            G.x = mA.x;               G.y = mA.y - dCo;
            R.x = G.x + 0.5f*(dLo + dCo);   R.y = mA.y;
            Bv.x = G.x + 0.5f*(du0 + dd0);
            Bv.y = G.y + 0.25f*(du0 + du2 + dd0 + dd2);

            __stcs(reinterpret_cast<float2*>(outr + o), R);
            __stcs(reinterpret_cast<float2*>(outg + o), G);
            __stcs(reinterpret_cast<float2*>(outb + o), Bv);
        }

        // ---- chroma odd row y+1 (B G) ----
        {
            float d0 = dOdd_cur;
            float d2 = __shfl_down_sync(FULLMASK, dOdd_cur, 1);
            if (rsel) d2 = xr0 ? d0 : hR_cur;
            float dub = dEv_cur, ddb = dEv_next;
            float dua = __shfl_up_sync(FULLMASK, dEv_cur, 1);
            float dda = __shfl_up_sync(FULLMASK, dEv_next, 1);
            if (haloL) { dua = xl0 ? dub : hL_cur; dda = xl0 ? ddb : hL_next; }
            if (y + 1 == H - 1) { dda = dua; ddb = dub; }   // zero-pad mirror at bottom

            float2 G, R, Bv;
            G.x = mB.x - d0;          G.y = mB.y;
            Bv.x = mB.x;              Bv.y = G.y + 0.5f*(d0 + d2);
            R.x = G.x + 0.25f*(dua + dub + dda + ddb);
            R.y = G.y + 0.5f*(dub + ddb);

            __stcs(reinterpret_cast<float2*>(outr + o + W), R);
            __stcs(reinterpret_cast<float2*>(outg + o + W), G);
            __stcs(reinterpret_cast<float2*>(outb + o + W), Bv);
        }

        // ---- shift pipeline ----
        mA = mC; mB = mD; mC = nmC; mD = nmD;
        qA = qC; qB = qD; qC = nqC; qD = nqD;
        dOdd_prev = dOdd_cur; dEv_cur = dEv_next;
        hL_cur = hL_next; hR_prev = hR_cur;
    }
}

extern "C" void kernel_launch(void* const* d_in, const int* in_sizes, int n_in,
                              void* d_out, int out_size)
{
    const float* m         = (const float*)d_in[0];
    const float* gfilt     = (const float*)d_in[1];
    const float* grad_filt = (const float*)d_in[2];
    float* out             = (float*)d_out;

    const int H = 1024, W = 1024;
    const int B = in_sizes[0] / (H * W);

    const int xblocks = W / 512;             // 8 warps * 64 px
    const int nys     = H / STRIPH;
    dim3 grid(xblocks * nys * B);
    demosaick_kernel<<<grid, NTHREADS>>>(m, gfilt, grad_filt, out, H, W);
}